// round 16
// baseline (speedup 1.0000x reference)
#include <cuda_runtime.h>
#include <cuda_fp16.h>
#include <cstdint>

// ---------------------------------------------------------------------------
// LinearAttention on GB300 — round 16:
//  * rowsum fused into GEMM1 epilogue (shfl + atomicAdd); rowsum pass deleted
//  * gemm_m: 2-stage pipeline -> 2 CTAs/SM
//  * g_sum zeroed inside conv_wq2
// ---------------------------------------------------------------------------

#define NB     8
#define CDIM   512
#define NSEQ   4096
#define HEADS  8
#define DHEAD  64
#define KV     1024
#define KREAL  512
#define KP2    1024
#define QSCALE 0.125f
#define NSPL   8

__device__ __half  g_kvh [NB * KV * NSEQ];      // expk rows 0-511, v rows 512-1023
__device__ __half  g_xh  [NB * CDIM * NSEQ];
__device__ __half  g_wh  [KV * KREAL];
__device__ __half  g_wq2 [2 * CDIM * CDIM];
__device__ float   g_sum [NB * CDIM];
__device__ float   g_part[NB * HEADS * NSPL * DHEAD * DHEAD];
__device__ float   g_ctx [NB * HEADS * DHEAD * DHEAD];
__device__ __half  g_A2  [NB * CDIM * KP2];
__device__ __half  g_Mh  [NB * CDIM * CDIM];

// ---------------------------------------------------------------------------
__device__ __forceinline__ void split_h(float v, __half& h, __half& l)
{
    h = __float2half_rn(v);
    l = __float2half_rn(v - __half2float(h));
}
__device__ __forceinline__ uint32_t pkh(__half a, __half b)
{
    __half2 t(a, b);
    return *reinterpret_cast<uint32_t*>(&t);
}
__device__ __forceinline__ void ldsm_x4(uint32_t& r0, uint32_t& r1,
                                        uint32_t& r2, uint32_t& r3, const void* p)
{
    uint32_t a = (uint32_t)__cvta_generic_to_shared(p);
    asm volatile("ldmatrix.sync.aligned.m8n8.x4.shared.b16 {%0,%1,%2,%3},[%4];"
                 : "=r"(r0), "=r"(r1), "=r"(r2), "=r"(r3) : "r"(a));
}
__device__ __forceinline__ void ldsm_x4_t(uint32_t& r0, uint32_t& r1,
                                          uint32_t& r2, uint32_t& r3, const void* p)
{
    uint32_t a = (uint32_t)__cvta_generic_to_shared(p);
    asm volatile("ldmatrix.sync.aligned.m8n8.x4.trans.shared.b16 {%0,%1,%2,%3},[%4];"
                 : "=r"(r0), "=r"(r1), "=r"(r2), "=r"(r3) : "r"(a));
}
__device__ __forceinline__ void mma16816(float* c, const uint32_t* a, const uint32_t* b)
{
    asm volatile(
        "mma.sync.aligned.m16n8k16.row.col.f32.f16.f16.f32 "
        "{%0,%1,%2,%3},{%4,%5,%6,%7},{%8,%9},{%0,%1,%2,%3};"
        : "+f"(c[0]), "+f"(c[1]), "+f"(c[2]), "+f"(c[3])
        : "r"(a[0]), "r"(a[1]), "r"(a[2]), "r"(a[3]), "r"(b[0]), "r"(b[1]));
}
__device__ __forceinline__ void cpa16(uint32_t dst, const void* src)
{
    asm volatile("cp.async.cg.shared.global [%0], [%1], 16;"
                 :: "r"(dst), "l"(src) : "memory");
}
__device__ __forceinline__ void cpa_commit()
{
    asm volatile("cp.async.commit_group;" ::: "memory");
}
template<int N>
__device__ __forceinline__ void cpa_wait()
{
    asm volatile("cp.async.wait_group %0;" :: "n"(N) : "memory");
}

#define ASTR  40
#define BSTR  264
#define A2B   (128 * ASTR * 2)        // 10240
#define B2B   (32 * BSTR * 2)         // 16896
#define G2STG (A2B + B2B)             // 27136
#define G2SMEM (3 * G2STG)            // 81408 (x2 CTAs/SM)

// ---------------------------------------------------------------------------
// gemm_h: C[b][M x N] = A[b][M x 512] @ B[b][512 x N] (+bias)
// 128x128 tile, 128 threads, BK=32, 3 stages, 2 CTAs/SM.
// OUTH: fp16 out; k-rows (m0<512) get exp() + fused row-sum atomics.
// ---------------------------------------------------------------------------
template<bool BIAS, bool OUTH>
__global__ void __launch_bounds__(128, 2) gemm_h(
    const __half* __restrict__ A, const __half* __restrict__ B,
    void* __restrict__ Cv, const float* __restrict__ bias,
    float* __restrict__ sums,
    long sA, long sB, long sC, int ldB, int ldC)
{
    extern __shared__ char sm[];
    const uint32_t smu = (uint32_t)__cvta_generic_to_shared(sm);

    const int b  = blockIdx.z;
    const __half* Ab = A + (long)b * sA;
    const __half* Bb = B + (long)b * sB;
    const int m0 = blockIdx.y * 128;
    const int n0 = blockIdx.x * 128;

    const int tid  = threadIdx.x;
    const int warp = tid >> 5;
    const int lane = tid & 31;
    const int wm   = warp >> 1;
    const int wn   = warp & 1;

    float acc[4][8][4];
    #pragma unroll
    for (int mi = 0; mi < 4; mi++)
        #pragma unroll
        for (int nj = 0; nj < 8; nj++)
            #pragma unroll
            for (int q = 0; q < 4; q++) acc[mi][nj][q] = 0.f;

    auto issue_stage = [&](int s, int kt) {
        const uint32_t as = smu + s * G2STG;
        const uint32_t bs = as + A2B;
        #pragma unroll
        for (int l = 0; l < 4; l++) {
            const int id  = tid + l * 128;
            const int row = id >> 2, c8 = (id & 3) * 8;
            cpa16(as + row * (ASTR * 2) + c8 * 2,
                  Ab + (long)(m0 + row) * KREAL + kt + c8);
        }
        #pragma unroll
        for (int l = 0; l < 4; l++) {
            const int id  = tid + l * 128;
            const int row = id >> 4, c8 = (id & 15) * 8;
            cpa16(bs + row * (BSTR * 2) + c8 * 2,
                  Bb + (long)(kt + row) * ldB + n0 + c8);
        }
    };

    const int S = KREAL / 32;
    issue_stage(0, 0);  cpa_commit();
    issue_stage(1, 32); cpa_commit();

    for (int t = 0; t < S; t++) {
        cpa_wait<1>();
        __syncthreads();

        if (t + 2 < S) issue_stage((t + 2) % 3, (t + 2) * 32);
        cpa_commit();

        const int s = t % 3;
        const __half* As = (const __half*)(sm + s * G2STG);
        const __half* Bs = (const __half*)(sm + s * G2STG + A2B);

        #pragma unroll
        for (int ks = 0; ks < 32; ks += 16) {
            uint32_t af[4][4];
            #pragma unroll
            for (int mi = 0; mi < 4; mi++)
                ldsm_x4(af[mi][0], af[mi][1], af[mi][2], af[mi][3],
                        As + (wm * 64 + mi * 16 + (lane & 15)) * ASTR
                           + ks + (lane >> 4) * 8);
            uint32_t bf[8][2];
            #pragma unroll
            for (int ni = 0; ni < 4; ni++) {
                uint32_t r0, r1, r2, r3;
                ldsm_x4_t(r0, r1, r2, r3,
                          Bs + (ks + (lane & 15)) * BSTR
                             + wn * 64 + ni * 16 + (lane >> 4) * 8);
                bf[2 * ni][0] = r0; bf[2 * ni][1] = r1;
                bf[2 * ni + 1][0] = r2; bf[2 * ni + 1][1] = r3;
            }
            #pragma unroll
            for (int mi = 0; mi < 4; mi++)
                #pragma unroll
                for (int nj = 0; nj < 8; nj++)
                    mma16816(acc[mi][nj], af[mi], bf[nj]);
        }
        __syncthreads();
    }

    const bool expk = OUTH && (m0 < CDIM);
    #pragma unroll
    for (int mi = 0; mi < 4; mi++) {
        const int row = m0 + wm * 64 + mi * 16 + (lane >> 2);
        const float b0 = BIAS ? bias[row]     : 0.f;
        const float b8 = BIAS ? bias[row + 8] : 0.f;
        float rs0 = 0.f, rs8 = 0.f;
        #pragma unroll
        for (int nj = 0; nj < 8; nj++) {
            const int col = n0 + wn * 64 + nj * 8 + 2 * (lane & 3);
            float v0 = acc[mi][nj][0] + b0, v1 = acc[mi][nj][1] + b0;
            float v2 = acc[mi][nj][2] + b8, v3 = acc[mi][nj][3] + b8;
            if (OUTH) {
                __half* Ch = (__half*)Cv + (long)b * sC;
                if (expk) {
                    v0 = __expf(v0); v1 = __expf(v1);
                    v2 = __expf(v2); v3 = __expf(v3);
                    rs0 += v0 + v1; rs8 += v2 + v3;
                }
                *(__half2*)(Ch + (long)row * ldC + col)       = __floats2half2_rn(v0, v1);
                *(__half2*)(Ch + (long)(row + 8) * ldC + col) = __floats2half2_rn(v2, v3);
            } else {
                float* Cf = (float*)Cv + (long)b * sC;
                *(float2*)(Cf + (long)row * ldC + col)       = make_float2(v0, v1);
                *(float2*)(Cf + (long)(row + 8) * ldC + col) = make_float2(v2, v3);
            }
        }
        if (expk) {
            // reduce over the 4 lanes that share this row (same lane>>2)
            rs0 += __shfl_xor_sync(0xFFFFFFFFu, rs0, 1);
            rs0 += __shfl_xor_sync(0xFFFFFFFFu, rs0, 2);
            rs8 += __shfl_xor_sync(0xFFFFFFFFu, rs8, 1);
            rs8 += __shfl_xor_sync(0xFFFFFFFFu, rs8, 2);
            if ((lane & 3) == 0) {
                atomicAdd(&sums[b * CDIM + row],     rs0);
                atomicAdd(&sums[b * CDIM + row + 8], rs8);
            }
        }
    }
}

// ---------------------------------------------------------------------------
// gemm_m: M = Ah@B0 + Al@B0 + Ah@B1 (exact split), 128x128, 128 thr,
// 2-stage cp.async, 2 CTAs/SM, fp16 out.
// ---------------------------------------------------------------------------
#define MSTG  (2 * A2B + 2 * B2B)     // 54272
#define MSMEM (2 * MSTG)              // 108544 (x2 CTAs = 217K < 227K)

__global__ void __launch_bounds__(128, 2) gemm_m_k(
    const __half* __restrict__ A, const __half* __restrict__ B,
    __half* __restrict__ C, long sA, long sC)
{
    extern __shared__ char sm[];
    const uint32_t smu = (uint32_t)__cvta_generic_to_shared(sm);

    const int b  = blockIdx.z;
    const __half* Ab = A + (long)b * sA;
    __half*       Cb = C + (long)b * sC;
    const int m0 = blockIdx.y * 128;
    const int n0 = blockIdx.x * 128;

    const int tid  = threadIdx.x;
    const int warp = tid >> 5;
    const int lane = tid & 31;
    const int wm   = warp >> 1;
    const int wn   = warp & 1;

    float acc[4][8][4];
    #pragma unroll
    for (int mi = 0; mi < 4; mi++)
        #pragma unroll
        for (int nj = 0; nj < 8; nj++)
            #pragma unroll
            for (int q = 0; q < 4; q++) acc[mi][nj][q] = 0.f;

    auto issue_stage = [&](int s, int kt) {
        const uint32_t ah = smu + s * MSTG;
        const uint32_t al = ah + A2B;
        const uint32_t bs = al + A2B;
        #pragma unroll
        for (int l = 0; l < 4; l++) {
            const int id  = tid + l * 128;
            const int row = id >> 2, c8 = (id & 3) * 8;
            const __half* arow = Ab + (long)(m0 + row) * KP2 + kt + c8;
            cpa16(ah + row * (ASTR * 2) + c8 * 2, arow);
            cpa16(al + row * (ASTR * 2) + c8 * 2, arow + KREAL);
        }
        #pragma unroll
        for (int p = 0; p < 2; p++)
            #pragma unroll
            for (int l = 0; l < 4; l++) {
                const int id  = tid + l * 128;
                const int row = id >> 4, c8 = (id & 15) * 8;
                cpa16(bs + p * B2B + row * (BSTR * 2) + c8 * 2,
                      B + (long)p * CDIM * CDIM + (long)(kt + row) * CDIM + n0 + c8);
            }
    };

    const int S = KREAL / 32;              // 16
    issue_stage(0, 0);  cpa_commit();
    issue_stage(1, 32); cpa_commit();

    for (int t = 0; t < S; t++) {
        cpa_wait<1>();
        __syncthreads();

        const int s = t & 1;
        const __half* Ah = (const __half*)(sm + s * MSTG);
        const __half* Al = (const __half*)(sm + s * MSTG + A2B);
        const __half* Bs = (const __half*)(sm + s * MSTG + 2 * A2B);

        #pragma unroll
        for (int ks = 0; ks < 32; ks += 16) {
            uint32_t afh[4][4], afl[4][4];
            #pragma unroll
            for (int mi = 0; mi < 4; mi++) {
                const int arow = wm * 64 + mi * 16 + (lane & 15);
                const int acol = ks + (lane >> 4) * 8;
                ldsm_x4(afh[mi][0], afh[mi][1], afh[mi][2], afh[mi][3],
                        Ah + arow * ASTR + acol);
                ldsm_x4(afl[mi][0], afl[mi][1], afl[mi][2], afl[mi][3],
                        Al + arow * ASTR + acol);
            }
            uint32_t bfr[2][8][2];
            #pragma unroll
            for (int p = 0; p < 2; p++)
                #pragma unroll
                for (int ni = 0; ni < 4; ni++) {
                    uint32_t r0, r1, r2, r3;
                    ldsm_x4_t(r0, r1, r2, r3,
                              Bs + p * B2B / 2 + (ks + (lane & 15)) * BSTR
                                 + wn * 64 + ni * 16 + (lane >> 4) * 8);
                    bfr[p][2 * ni][0] = r0; bfr[p][2 * ni][1] = r1;
                    bfr[p][2 * ni + 1][0] = r2; bfr[p][2 * ni + 1][1] = r3;
                }
            #pragma unroll
            for (int mi = 0; mi < 4; mi++)
                #pragma unroll
                for (int nj = 0; nj < 8; nj++) {
                    mma16816(acc[mi][nj], afh[mi], bfr[0][nj]);
                    mma16816(acc[mi][nj], afl[mi], bfr[0][nj]);
                    mma16816(acc[mi][nj], afh[mi], bfr[1][nj]);
                }
        }
        __syncthreads();
        if (t + 2 < S) issue_stage(s, (t + 2) * 32);   // reuse buffer t (safe: compute done)
        cpa_commit();
    }

    #pragma unroll
    for (int mi = 0; mi < 4; mi++) {
        const int row = m0 + wm * 64 + mi * 16 + (lane >> 2);
        #pragma unroll
        for (int nj = 0; nj < 8; nj++) {
            const int col = n0 + wn * 64 + nj * 8 + 2 * (lane & 3);
            *(__half2*)(Cb + (long)row * CDIM + col) =
                __floats2half2_rn(acc[mi][nj][0], acc[mi][nj][1]);
            *(__half2*)(Cb + (long)(row + 8) * CDIM + col) =
                __floats2half2_rn(acc[mi][nj][2], acc[mi][nj][3]);
        }
    }
}

// ---------------------------------------------------------------------------
// Context tensor GEMM (unchanged)
// ---------------------------------------------------------------------------
#define ASTR2 72
__global__ void __launch_bounds__(128) ctx64_k(
    const __half* __restrict__ kvh, float* __restrict__ part)
{
    __shared__ __half ks[2][64][ASTR2];
    __shared__ __half vs[2][64][ASTR2];

    const int s  = blockIdx.x;
    const int bh = blockIdx.y;
    const int b  = bh >> 3;
    const int h  = bh & 7;
    const __half* kb = kvh + (long)b * KV * NSEQ + (long)(h * DHEAD) * NSEQ + s * 512;
    const __half* vb = kvh + (long)b * KV * NSEQ + (long)(CDIM + h * DHEAD) * NSEQ + s * 512;

    const int tid  = threadIdx.x;
    const int warp = tid >> 5;
    const int lane = tid & 31;
    const int wm   = warp >> 1;
    const int wn   = warp & 1;

    float acc[2][4][4];
    #pragma unroll
    for (int mi = 0; mi < 2; mi++)
        #pragma unroll
        for (int nj = 0; nj < 4; nj++)
            #pragma unroll
            for (int q = 0; q < 4; q++) acc[mi][nj][q] = 0.f;

    auto issue_stage = [&](int st, int kt) {
        const uint32_t ka = (uint32_t)__cvta_generic_to_shared(&ks[st][0][0]);
        const uint32_t va = (uint32_t)__cvta_generic_to_shared(&vs[st][0][0]);
        #pragma unroll
        for (int l = 0; l < 4; l++) {
            const int id  = tid + l * 128;
            const int row = id >> 3, c8 = (id & 7) * 8;
            cpa16(ka + row * 144 + c8 * 2, kb + (long)row * NSEQ + kt + c8);
            cpa16(va + row * 144 + c8 * 2, vb + (long)row * NSEQ + kt + c8);
        }
    };

    const int S = 512 / 64;
    issue_stage(0, 0); cpa_commit();

    for (int t = 0; t < S; t++) {
        cpa_wait<0>();
        __syncthreads();
        if (t + 1 < S) issue_stage((t + 1) & 1, (t + 1) * 64);
        cpa_commit();

        const int st = t & 1;
        #pragma unroll
        for (int k16 = 0; k16 < 4; k16++) {
            uint32_t af[2][4];
            #pragma unroll
            for (int mi = 0; mi < 2; mi++)
                ldsm_x4(af[mi][0], af[mi][1], af[mi][2], af[mi][3],
                        &ks[st][wm * 32 + mi * 16 + (lane & 15)]
                           [k16 * 16 + (lane >> 4) * 8]);
            uint32_t bf[4][2];
            #pragma unroll
            for (int ni = 0; ni < 2; ni++) {
                uint32_t r0, r1, r2, r3;
                ldsm_x4(r0, r1, r2, r3,
                        &vs[st][wn * 32 + ni * 16 + (lane & 15)]
                           [k16 * 16 + (lane >> 4) * 8]);
                bf[2 * ni][0] = r0; bf[2 * ni][1] = r2;
                bf[2 * ni + 1][0] = r1; bf[2 * ni + 1][1] = r3;
            }
            #pragma unroll
            for (int mi = 0; mi < 2; mi++)
                #pragma unroll
                for (int nj = 0; nj < 4; nj++)
                    mma16816(acc[mi][nj], af[mi], bf[nj]);
        }
        __syncthreads();
    }

    float* pp = part + ((long)bh * NSPL + s) * (DHEAD * DHEAD);
    #pragma unroll
    for (int mi = 0; mi < 2; mi++) {
        const int d = wm * 32 + mi * 16 + (lane >> 2);
        #pragma unroll
        for (int nj = 0; nj < 4; nj++) {
            const int e = wn * 32 + nj * 8 + 2 * (lane & 3);
            pp[d * DHEAD + e]           = acc[mi][nj][0];
            pp[d * DHEAD + e + 1]       = acc[mi][nj][1];
            pp[(d + 8) * DHEAD + e]     = acc[mi][nj][2];
            pp[(d + 8) * DHEAD + e + 1] = acc[mi][nj][3];
        }
    }
}

__global__ void __launch_bounds__(256) context_reduce_k(
    const float* __restrict__ part, const float* __restrict__ sums,
    float* __restrict__ ctx)
{
    const int idx = blockIdx.x * 256 + threadIdx.x;
    const int bh  = idx >> 12;
    const int de  = idx & 4095;
    const int d   = de >> 6;
    const int b   = bh >> 3;
    const int h   = bh & 7;
    float ssum = 0.f;
    #pragma unroll
    for (int s = 0; s < NSPL; s++)
        ssum += part[((long)bh * NSPL + s) * 4096 + de];
    ctx[(long)bh * 4096 + de] = ssum / sums[b * CDIM + h * DHEAD + d];
}

// build A and write split (hi|lo) planes directly into g_A2
__global__ void __launch_bounds__(256) build_A2_k(
    const float* __restrict__ w_out, const float* __restrict__ ctx,
    __half* __restrict__ A2)
{
    const long idx = (long)blockIdx.x * 256 + threadIdx.x;
    const int b   = (int)(idx >> 18);
    const int rem = (int)(idx & 262143);
    const int o   = rem >> 9;
    const int i   = rem & 511;
    const int h   = i >> 6;
    const int d   = i & 63;
    const float* wrow = w_out + (long)o * CDIM + h * DHEAD;
    const float* crow = ctx + ((long)(b * HEADS + h) * DHEAD + d) * DHEAD;
    float ssum = 0.f;
    #pragma unroll
    for (int e = 0; e < DHEAD; e++)
        ssum += wrow[e] * crow[e];
    ssum *= QSCALE;
    __half hh, ll;
    split_h(ssum, hh, ll);
    __half* row = A2 + ((long)b * CDIM + o) * KP2;
    row[i]         = hh;
    row[i + KREAL] = ll;
}

// ---------------------------------------------------------------------------
// Converters
// ---------------------------------------------------------------------------
__global__ void __launch_bounds__(256) conv_h_k(
    const float* __restrict__ in, __half* __restrict__ out, long quads)
{
    const long i4 = (long)blockIdx.x * 256 + threadIdx.x;
    if (i4 >= quads) return;
    float4 v = ((const float4*)in)[i4];
    __half2 a(__float2half_rn(v.x), __float2half_rn(v.y));
    __half2 b(__float2half_rn(v.z), __float2half_rn(v.w));
    uint2 o;
    o.x = *reinterpret_cast<uint32_t*>(&a);
    o.y = *reinterpret_cast<uint32_t*>(&b);
    ((uint2*)out)[i4] = o;
}

// Wq planes + zero g_sum (runs before GEMM1's atomics in stream order)
__global__ void __launch_bounds__(256) conv_wq2_k(
    const float* __restrict__ in, __half* __restrict__ out, float* __restrict__ sums)
{
    const long idx = (long)blockIdx.x * 256 + threadIdx.x;
    if (idx < NB * CDIM / 4)
        ((float4*)sums)[idx] = make_float4(0.f, 0.f, 0.f, 0.f);
    const int r = (int)(idx >> 7);
    const int c = (int)(idx & 127) * 4;
    float4 v = *(const float4*)(in + (long)r * CDIM + c);
    __half h0, h1, h2, h3, l0, l1, l2, l3;
    split_h(v.x, h0, l0); split_h(v.y, h1, l1);
    split_h(v.z, h2, l2); split_h(v.w, h3, l3);
    __half* oh = out + (long)r * CDIM + c;
    *(uint2*)(oh)                     = make_uint2(pkh(h0, h1), pkh(h2, h3));
    *(uint2*)(oh + (long)CDIM * CDIM) = make_uint2(pkh(l0, l1), pkh(l2, l3));
}

// ---------------------------------------------------------------------------
extern "C" void kernel_launch(void* const* d_in, const int* in_sizes, int n_in,
                              void* d_out, int out_size)
{
    const float *x = nullptr, *w_qkv = nullptr, *w_out = nullptr, *b_out = nullptr;
    for (int i = 0; i < n_in; i++) {
        switch (in_sizes[i]) {
            case NB * CDIM * NSEQ:  x     = (const float*)d_in[i]; break;
            case 3 * CDIM * CDIM:   w_qkv = (const float*)d_in[i]; break;
            case CDIM * CDIM:       w_out = (const float*)d_in[i]; break;
            case CDIM:              b_out = (const float*)d_in[i]; break;
        }
    }
    float* out = (float*)d_out;

    float *sum_p, *part_p, *ctx_p;
    __half *kvh_p, *xh_p, *wh_p, *wq2_p, *A2_p, *Mh_p;
    cudaGetSymbolAddress((void**)&kvh_p,  g_kvh);
    cudaGetSymbolAddress((void**)&sum_p,  g_sum);
    cudaGetSymbolAddress((void**)&part_p, g_part);
    cudaGetSymbolAddress((void**)&ctx_p,  g_ctx);
    cudaGetSymbolAddress((void**)&xh_p,   g_xh);
    cudaGetSymbolAddress((void**)&wh_p,   g_wh);
    cudaGetSymbolAddress((void**)&wq2_p,  g_wq2);
    cudaGetSymbolAddress((void**)&A2_p,   g_A2);
    cudaGetSymbolAddress((void**)&Mh_p,   g_Mh);

    static bool attr_set = false;
    if (!attr_set) {
        cudaFuncSetAttribute(gemm_h<false, true>,
                             cudaFuncAttributeMaxDynamicSharedMemorySize, G2SMEM);
        cudaFuncSetAttribute(gemm_h<true, false>,
                             cudaFuncAttributeMaxDynamicSharedMemorySize, G2SMEM);
        cudaFuncSetAttribute(gemm_m_k,
                             cudaFuncAttributeMaxDynamicSharedMemorySize, MSMEM);
        attr_set = true;
    }

    // converters (conv_wq2 also zeroes g_sum)
    conv_h_k<<<(KV * KREAL / 4 + 255) / 256, 256>>>(
        w_qkv + (long)CDIM * CDIM, wh_p, (long)KV * KREAL / 4);
    conv_wq2_k<<<(CDIM * 128) / 256, 256>>>(w_qkv, wq2_p, sum_p);
    conv_h_k<<<((long)NB * CDIM * NSEQ / 4 + 255) / 256, 256>>>(
        x, xh_p, (long)NB * CDIM * NSEQ / 4);

    // kv = Wh @ xh -> fp16, exp + row-sum atomics fused on k rows
    {
        dim3 grid(NSEQ / 128, KV / 128, NB);
        gemm_h<false, true><<<grid, 128, G2SMEM>>>(wh_p, xh_p, kvh_p, nullptr, sum_p,
                                                   0L, (long)CDIM * NSEQ,
                                                   (long)KV * NSEQ, NSEQ, NSEQ);
    }
    // context tensor GEMM + normalized reduce
    {
        dim3 grid(NSPL, NB * HEADS);
        ctx64_k<<<grid, 128>>>(kvh_p, part_p);
        context_reduce_k<<<(NB * HEADS * DHEAD * DHEAD) / 256, 256>>>(part_p, sum_p, ctx_p);
    }
    // A2 = split(fold(w_out, ctx) * qscale)
    build_A2_k<<<(NB * CDIM * CDIM) / 256, 256>>>(w_out, ctx_p, A2_p);
    // Mh = fp16(A @ Wq) (exact split GEMM)
    {
        dim3 grid(CDIM / 128, CDIM / 128, NB);
        gemm_m_k<<<grid, 128, MSMEM>>>(A2_p, wq2_p, Mh_p,
                                       (long)CDIM * KP2, (long)CDIM * CDIM);
    }
    // out = Mh @ xh + b_out
    {
        dim3 grid(NSEQ / 128, CDIM / 128, NB);
        gemm_h<true, false><<<grid, 128, G2SMEM>>>(Mh_p, xh_p, out, b_out, nullptr,
                                                   (long)CDIM * CDIM, (long)CDIM * NSEQ,
                                                   (long)CDIM * NSEQ, NSEQ, NSEQ);
    }
}

// round 17
// speedup vs baseline: 2.4850x; 2.4850x over previous
#include <cuda_runtime.h>
#include <cuda_fp16.h>
#include <cstdint>

// ---------------------------------------------------------------------------
// LinearAttention on GB300 — round 17:
//  * revert R16 regressions (rowsum back to own pass; gemm_m back to 3-stage)
//  * build_A2 + context_reduce fused into one smem-tiled kernel
//    (ctx staged once per block; w_out row in regs; ~1GB -> ~35MB traffic)
// ---------------------------------------------------------------------------

#define NB     8
#define CDIM   512
#define NSEQ   4096
#define HEADS  8
#define DHEAD  64
#define KV     1024
#define KREAL  512
#define KP2    1024
#define QSCALE 0.125f
#define NSPL   8

__device__ __half  g_kvh [NB * KV * NSEQ];      // expk rows 0-511, v rows 512-1023
__device__ __half  g_xh  [NB * CDIM * NSEQ];
__device__ __half  g_wh  [KV * KREAL];
__device__ __half  g_wq2 [2 * CDIM * CDIM];
__device__ float   g_sum [NB * CDIM];
__device__ float   g_part[NB * HEADS * NSPL * DHEAD * DHEAD];
__device__ __half  g_A2  [NB * CDIM * KP2];
__device__ __half  g_Mh  [NB * CDIM * CDIM];

// ---------------------------------------------------------------------------
__device__ __forceinline__ void split_h(float v, __half& h, __half& l)
{
    h = __float2half_rn(v);
    l = __float2half_rn(v - __half2float(h));
}
__device__ __forceinline__ uint32_t pkh(__half a, __half b)
{
    __half2 t(a, b);
    return *reinterpret_cast<uint32_t*>(&t);
}
__device__ __forceinline__ void ldsm_x4(uint32_t& r0, uint32_t& r1,
                                        uint32_t& r2, uint32_t& r3, const void* p)
{
    uint32_t a = (uint32_t)__cvta_generic_to_shared(p);
    asm volatile("ldmatrix.sync.aligned.m8n8.x4.shared.b16 {%0,%1,%2,%3},[%4];"
                 : "=r"(r0), "=r"(r1), "=r"(r2), "=r"(r3) : "r"(a));
}
__device__ __forceinline__ void ldsm_x4_t(uint32_t& r0, uint32_t& r1,
                                          uint32_t& r2, uint32_t& r3, const void* p)
{
    uint32_t a = (uint32_t)__cvta_generic_to_shared(p);
    asm volatile("ldmatrix.sync.aligned.m8n8.x4.trans.shared.b16 {%0,%1,%2,%3},[%4];"
                 : "=r"(r0), "=r"(r1), "=r"(r2), "=r"(r3) : "r"(a));
}
__device__ __forceinline__ void mma16816(float* c, const uint32_t* a, const uint32_t* b)
{
    asm volatile(
        "mma.sync.aligned.m16n8k16.row.col.f32.f16.f16.f32 "
        "{%0,%1,%2,%3},{%4,%5,%6,%7},{%8,%9},{%0,%1,%2,%3};"
        : "+f"(c[0]), "+f"(c[1]), "+f"(c[2]), "+f"(c[3])
        : "r"(a[0]), "r"(a[1]), "r"(a[2]), "r"(a[3]), "r"(b[0]), "r"(b[1]));
}
__device__ __forceinline__ void cpa16(uint32_t dst, const void* src)
{
    asm volatile("cp.async.cg.shared.global [%0], [%1], 16;"
                 :: "r"(dst), "l"(src) : "memory");
}
__device__ __forceinline__ void cpa_commit()
{
    asm volatile("cp.async.commit_group;" ::: "memory");
}
template<int N>
__device__ __forceinline__ void cpa_wait()
{
    asm volatile("cp.async.wait_group %0;" :: "n"(N) : "memory");
}

#define ASTR  40
#define BSTR  264
#define A2B   (128 * ASTR * 2)        // 10240
#define B2B   (32 * BSTR * 2)         // 16896
#define G2STG (A2B + B2B)             // 27136
#define G2SMEM (3 * G2STG)            // 81408 (x2 CTAs/SM)

// ---------------------------------------------------------------------------
// gemm_h: C[b][M x N] = A[b][M x 512] @ B[b][512 x N] (+bias)
// 128x128 tile, 128 threads, BK=32, 3 stages, 2 CTAs/SM.
// OUTH: fp16 out, exp fused on k-rows (m0 < 512).  (R15-identical)
// ---------------------------------------------------------------------------
template<bool BIAS, bool OUTH>
__global__ void __launch_bounds__(128, 2) gemm_h(
    const __half* __restrict__ A, const __half* __restrict__ B,
    void* __restrict__ Cv, const float* __restrict__ bias,
    long sA, long sB, long sC, int ldB, int ldC)
{
    extern __shared__ char sm[];
    const uint32_t smu = (uint32_t)__cvta_generic_to_shared(sm);

    const int b  = blockIdx.z;
    const __half* Ab = A + (long)b * sA;
    const __half* Bb = B + (long)b * sB;
    const int m0 = blockIdx.y * 128;
    const int n0 = blockIdx.x * 128;

    const int tid  = threadIdx.x;
    const int warp = tid >> 5;
    const int lane = tid & 31;
    const int wm   = warp >> 1;
    const int wn   = warp & 1;

    float acc[4][8][4];
    #pragma unroll
    for (int mi = 0; mi < 4; mi++)
        #pragma unroll
        for (int nj = 0; nj < 8; nj++)
            #pragma unroll
            for (int q = 0; q < 4; q++) acc[mi][nj][q] = 0.f;

    auto issue_stage = [&](int s, int kt) {
        const uint32_t as = smu + s * G2STG;
        const uint32_t bs = as + A2B;
        #pragma unroll
        for (int l = 0; l < 4; l++) {
            const int id  = tid + l * 128;
            const int row = id >> 2, c8 = (id & 3) * 8;
            cpa16(as + row * (ASTR * 2) + c8 * 2,
                  Ab + (long)(m0 + row) * KREAL + kt + c8);
        }
        #pragma unroll
        for (int l = 0; l < 4; l++) {
            const int id  = tid + l * 128;
            const int row = id >> 4, c8 = (id & 15) * 8;
            cpa16(bs + row * (BSTR * 2) + c8 * 2,
                  Bb + (long)(kt + row) * ldB + n0 + c8);
        }
    };

    const int S = KREAL / 32;
    issue_stage(0, 0);  cpa_commit();
    issue_stage(1, 32); cpa_commit();

    for (int t = 0; t < S; t++) {
        cpa_wait<1>();
        __syncthreads();

        if (t + 2 < S) issue_stage((t + 2) % 3, (t + 2) * 32);
        cpa_commit();

        const int s = t % 3;
        const __half* As = (const __half*)(sm + s * G2STG);
        const __half* Bs = (const __half*)(sm + s * G2STG + A2B);

        #pragma unroll
        for (int ks = 0; ks < 32; ks += 16) {
            uint32_t af[4][4];
            #pragma unroll
            for (int mi = 0; mi < 4; mi++)
                ldsm_x4(af[mi][0], af[mi][1], af[mi][2], af[mi][3],
                        As + (wm * 64 + mi * 16 + (lane & 15)) * ASTR
                           + ks + (lane >> 4) * 8);
            uint32_t bf[8][2];
            #pragma unroll
            for (int ni = 0; ni < 4; ni++) {
                uint32_t r0, r1, r2, r3;
                ldsm_x4_t(r0, r1, r2, r3,
                          Bs + (ks + (lane & 15)) * BSTR
                             + wn * 64 + ni * 16 + (lane >> 4) * 8);
                bf[2 * ni][0] = r0; bf[2 * ni][1] = r1;
                bf[2 * ni + 1][0] = r2; bf[2 * ni + 1][1] = r3;
            }
            #pragma unroll
            for (int mi = 0; mi < 4; mi++)
                #pragma unroll
                for (int nj = 0; nj < 8; nj++)
                    mma16816(acc[mi][nj], af[mi], bf[nj]);
        }
        __syncthreads();
    }

    const bool expk = OUTH && (m0 < CDIM);
    #pragma unroll
    for (int mi = 0; mi < 4; mi++) {
        const int row = m0 + wm * 64 + mi * 16 + (lane >> 2);
        const float b0 = BIAS ? bias[row]     : 0.f;
        const float b8 = BIAS ? bias[row + 8] : 0.f;
        #pragma unroll
        for (int nj = 0; nj < 8; nj++) {
            const int col = n0 + wn * 64 + nj * 8 + 2 * (lane & 3);
            float v0 = acc[mi][nj][0] + b0, v1 = acc[mi][nj][1] + b0;
            float v2 = acc[mi][nj][2] + b8, v3 = acc[mi][nj][3] + b8;
            if (OUTH) {
                __half* Ch = (__half*)Cv + (long)b * sC;
                if (expk) {
                    v0 = __expf(v0); v1 = __expf(v1);
                    v2 = __expf(v2); v3 = __expf(v3);
                }
                *(__half2*)(Ch + (long)row * ldC + col)       = __floats2half2_rn(v0, v1);
                *(__half2*)(Ch + (long)(row + 8) * ldC + col) = __floats2half2_rn(v2, v3);
            } else {
                float* Cf = (float*)Cv + (long)b * sC;
                *(float2*)(Cf + (long)row * ldC + col)       = make_float2(v0, v1);
                *(float2*)(Cf + (long)(row + 8) * ldC + col) = make_float2(v2, v3);
            }
        }
    }
}

// ---------------------------------------------------------------------------
// gemm_m: M = Ah@B0 + Al@B0 + Ah@B1 (exact split), 128x128, 128 thr,
// 3-stage cp.async (R15 config), fp16 out.
// ---------------------------------------------------------------------------
#define MSTG  (2 * A2B + 2 * B2B)     // 54272
#define MSMEM (3 * MSTG)              // 162816

__global__ void __launch_bounds__(128, 1) gemm_m_k(
    const __half* __restrict__ A, const __half* __restrict__ B,
    __half* __restrict__ C, long sA, long sC)
{
    extern __shared__ char sm[];
    const uint32_t smu = (uint32_t)__cvta_generic_to_shared(sm);

    const int b  = blockIdx.z;
    const __half* Ab = A + (long)b * sA;
    __half*       Cb = C + (long)b * sC;
    const int m0 = blockIdx.y * 128;
    const int n0 = blockIdx.x * 128;

    const int tid  = threadIdx.x;
    const int warp = tid >> 5;
    const int lane = tid & 31;
    const int wm   = warp >> 1;
    const int wn   = warp & 1;

    float acc[4][8][4];
    #pragma unroll
    for (int mi = 0; mi < 4; mi++)
        #pragma unroll
        for (int nj = 0; nj < 8; nj++)
            #pragma unroll
            for (int q = 0; q < 4; q++) acc[mi][nj][q] = 0.f;

    auto issue_stage = [&](int s, int kt) {
        const uint32_t ah = smu + s * MSTG;
        const uint32_t al = ah + A2B;
        const uint32_t bs = al + A2B;
        #pragma unroll
        for (int l = 0; l < 4; l++) {
            const int id  = tid + l * 128;
            const int row = id >> 2, c8 = (id & 3) * 8;
            const __half* arow = Ab + (long)(m0 + row) * KP2 + kt + c8;
            cpa16(ah + row * (ASTR * 2) + c8 * 2, arow);
            cpa16(al + row * (ASTR * 2) + c8 * 2, arow + KREAL);
        }
        #pragma unroll
        for (int p = 0; p < 2; p++)
            #pragma unroll
            for (int l = 0; l < 4; l++) {
                const int id  = tid + l * 128;
                const int row = id >> 4, c8 = (id & 15) * 8;
                cpa16(bs + p * B2B + row * (BSTR * 2) + c8 * 2,
                      B + (long)p * CDIM * CDIM + (long)(kt + row) * CDIM + n0 + c8);
            }
    };

    const int S = KREAL / 32;
    issue_stage(0, 0);  cpa_commit();
    issue_stage(1, 32); cpa_commit();

    for (int t = 0; t < S; t++) {
        cpa_wait<1>();
        __syncthreads();

        if (t + 2 < S) issue_stage((t + 2) % 3, (t + 2) * 32);
        cpa_commit();

        const int s = t % 3;
        const __half* Ah = (const __half*)(sm + s * MSTG);
        const __half* Al = (const __half*)(sm + s * MSTG + A2B);
        const __half* Bs = (const __half*)(sm + s * MSTG + 2 * A2B);

        #pragma unroll
        for (int ks = 0; ks < 32; ks += 16) {
            uint32_t afh[4][4], afl[4][4];
            #pragma unroll
            for (int mi = 0; mi < 4; mi++) {
                const int arow = wm * 64 + mi * 16 + (lane & 15);
                const int acol = ks + (lane >> 4) * 8;
                ldsm_x4(afh[mi][0], afh[mi][1], afh[mi][2], afh[mi][3],
                        Ah + arow * ASTR + acol);
                ldsm_x4(afl[mi][0], afl[mi][1], afl[mi][2], afl[mi][3],
                        Al + arow * ASTR + acol);
            }
            uint32_t bfr[2][8][2];
            #pragma unroll
            for (int p = 0; p < 2; p++)
                #pragma unroll
                for (int ni = 0; ni < 4; ni++) {
                    uint32_t r0, r1, r2, r3;
                    ldsm_x4_t(r0, r1, r2, r3,
                              Bs + p * B2B / 2 + (ks + (lane & 15)) * BSTR
                                 + wn * 64 + ni * 16 + (lane >> 4) * 8);
                    bfr[p][2 * ni][0] = r0; bfr[p][2 * ni][1] = r1;
                    bfr[p][2 * ni + 1][0] = r2; bfr[p][2 * ni + 1][1] = r3;
                }
            #pragma unroll
            for (int mi = 0; mi < 4; mi++)
                #pragma unroll
                for (int nj = 0; nj < 8; nj++) {
                    mma16816(acc[mi][nj], afh[mi], bfr[0][nj]);
                    mma16816(acc[mi][nj], afl[mi], bfr[0][nj]);
                    mma16816(acc[mi][nj], afh[mi], bfr[1][nj]);
                }
        }
        __syncthreads();
    }

    #pragma unroll
    for (int mi = 0; mi < 4; mi++) {
        const int row = m0 + wm * 64 + mi * 16 + (lane >> 2);
        #pragma unroll
        for (int nj = 0; nj < 8; nj++) {
            const int col = n0 + wn * 64 + nj * 8 + 2 * (lane & 3);
            *(__half2*)(Cb + (long)row * CDIM + col) =
                __floats2half2_rn(acc[mi][nj][0], acc[mi][nj][1]);
            *(__half2*)(Cb + (long)(row + 8) * CDIM + col) =
                __floats2half2_rn(acc[mi][nj][2], acc[mi][nj][3]);
        }
    }
}

// ---------------------------------------------------------------------------
// Context tensor GEMM (unchanged)
// ---------------------------------------------------------------------------
#define ASTR2 72
__global__ void __launch_bounds__(128) ctx64_k(
    const __half* __restrict__ kvh, float* __restrict__ part)
{
    __shared__ __half ks[2][64][ASTR2];
    __shared__ __half vs[2][64][ASTR2];

    const int s  = blockIdx.x;
    const int bh = blockIdx.y;
    const int b  = bh >> 3;
    const int h  = bh & 7;
    const __half* kb = kvh + (long)b * KV * NSEQ + (long)(h * DHEAD) * NSEQ + s * 512;
    const __half* vb = kvh + (long)b * KV * NSEQ + (long)(CDIM + h * DHEAD) * NSEQ + s * 512;

    const int tid  = threadIdx.x;
    const int warp = tid >> 5;
    const int lane = tid & 31;
    const int wm   = warp >> 1;
    const int wn   = warp & 1;

    float acc[2][4][4];
    #pragma unroll
    for (int mi = 0; mi < 2; mi++)
        #pragma unroll
        for (int nj = 0; nj < 4; nj++)
            #pragma unroll
            for (int q = 0; q < 4; q++) acc[mi][nj][q] = 0.f;

    auto issue_stage = [&](int st, int kt) {
        const uint32_t ka = (uint32_t)__cvta_generic_to_shared(&ks[st][0][0]);
        const uint32_t va = (uint32_t)__cvta_generic_to_shared(&vs[st][0][0]);
        #pragma unroll
        for (int l = 0; l < 4; l++) {
            const int id  = tid + l * 128;
            const int row = id >> 3, c8 = (id & 7) * 8;
            cpa16(ka + row * 144 + c8 * 2, kb + (long)row * NSEQ + kt + c8);
            cpa16(va + row * 144 + c8 * 2, vb + (long)row * NSEQ + kt + c8);
        }
    };

    const int S = 512 / 64;
    issue_stage(0, 0); cpa_commit();

    for (int t = 0; t < S; t++) {
        cpa_wait<0>();
        __syncthreads();
        if (t + 1 < S) issue_stage((t + 1) & 1, (t + 1) * 64);
        cpa_commit();

        const int st = t & 1;
        #pragma unroll
        for (int k16 = 0; k16 < 4; k16++) {
            uint32_t af[2][4];
            #pragma unroll
            for (int mi = 0; mi < 2; mi++)
                ldsm_x4(af[mi][0], af[mi][1], af[mi][2], af[mi][3],
                        &ks[st][wm * 32 + mi * 16 + (lane & 15)]
                           [k16 * 16 + (lane >> 4) * 8]);
            uint32_t bf[4][2];
            #pragma unroll
            for (int ni = 0; ni < 2; ni++) {
                uint32_t r0, r1, r2, r3;
                ldsm_x4(r0, r1, r2, r3,
                        &vs[st][wn * 32 + ni * 16 + (lane & 15)]
                           [k16 * 16 + (lane >> 4) * 8]);
                bf[2 * ni][0] = r0; bf[2 * ni][1] = r2;
                bf[2 * ni + 1][0] = r1; bf[2 * ni + 1][1] = r3;
            }
            #pragma unroll
            for (int mi = 0; mi < 2; mi++)
                #pragma unroll
                for (int nj = 0; nj < 4; nj++)
                    mma16816(acc[mi][nj], af[mi], bf[nj]);
        }
        __syncthreads();
    }

    float* pp = part + ((long)bh * NSPL + s) * (DHEAD * DHEAD);
    #pragma unroll
    for (int mi = 0; mi < 2; mi++) {
        const int d = wm * 32 + mi * 16 + (lane >> 2);
        #pragma unroll
        for (int nj = 0; nj < 4; nj++) {
            const int e = wn * 32 + nj * 8 + 2 * (lane & 3);
            pp[d * DHEAD + e]           = acc[mi][nj][0];
            pp[d * DHEAD + e + 1]       = acc[mi][nj][1];
            pp[(d + 8) * DHEAD + e]     = acc[mi][nj][2];
            pp[(d + 8) * DHEAD + e + 1] = acc[mi][nj][3];
        }
    }
}

// rowsum of expk rows (fp16) -> fp32 sums  (R15 version, separate pass)
__global__ void __launch_bounds__(256) rowsum_k(
    const __half* __restrict__ kvh, float* __restrict__ sums)
{
    const int row = blockIdx.x;
    const int b   = row >> 9;
    const int c   = row & 511;
    const __half2* p = (const __half2*)(kvh + (long)b * KV * NSEQ + (long)c * NSEQ);

    const int tid = threadIdx.x;
    __shared__ float red[256];
    float sum = 0.f;
    #pragma unroll
    for (int i = 0; i < 8; i++) {
        float2 v = __half22float2(p[tid + i * 256]);
        sum += v.x + v.y;
    }
    red[tid] = sum;
    __syncthreads();
    for (int st = 128; st > 0; st >>= 1) {
        if (tid < st) red[tid] += red[tid + st];
        __syncthreads();
    }
    if (tid == 0) sums[row] = red[0];
}

// ---------------------------------------------------------------------------
// Fused: reduce part over splits + normalize + fold w_out + qscale + split
// into A2.  Grid (HEADS, NB, 2); 256 threads; each thread one o-row.
// ctx staged in smem transposed [e][d]; broadcast reads (conflict-free).
// ---------------------------------------------------------------------------
__global__ void __launch_bounds__(256) build_A2f_k(
    const float* __restrict__ w_out, const float* __restrict__ part,
    const float* __restrict__ sums, __half* __restrict__ A2)
{
    const int h  = blockIdx.x;
    const int b  = blockIdx.y;
    const int oz = blockIdx.z;             // 0..1, o-range [oz*256, +256)
    const int bh = b * HEADS + h;
    const int tid = threadIdx.x;

    __shared__ float ctxs[64][65];         // [e][d]
    __shared__ float inv[64];

    if (tid < 64) inv[tid] = 1.f / sums[b * CDIM + h * DHEAD + tid];
    __syncthreads();

    for (int i = tid; i < 4096; i += 256) {
        const int d = i >> 6, e = i & 63;
        float ssum = 0.f;
        #pragma unroll
        for (int s = 0; s < NSPL; s++)
            ssum += part[((long)bh * NSPL + s) * 4096 + i];
        ctxs[e][d] = ssum * inv[d];
    }
    __syncthreads();

    const int o = oz * 256 + tid;
    float wr[64];
    const float* wrow = w_out + (long)o * CDIM + h * DHEAD;
    #pragma unroll
    for (int e = 0; e < 64; e++) wr[e] = wrow[e];

    __half* rowh = A2 + ((long)b * CDIM + o) * KP2 + h * DHEAD;
    #pragma unroll 4
    for (int d = 0; d < 64; d++) {
        float acc = 0.f;
        #pragma unroll
        for (int e = 0; e < 64; e++)
            acc += wr[e] * ctxs[e][d];
        acc *= QSCALE;
        __half hh, ll;
        split_h(acc, hh, ll);
        rowh[d]         = hh;
        rowh[d + KREAL] = ll;
    }
}

// ---------------------------------------------------------------------------
// Converters
// ---------------------------------------------------------------------------
__global__ void __launch_bounds__(256) conv_h_k(
    const float* __restrict__ in, __half* __restrict__ out, long quads)
{
    const long i4 = (long)blockIdx.x * 256 + threadIdx.x;
    if (i4 >= quads) return;
    float4 v = ((const float4*)in)[i4];
    __half2 a(__float2half_rn(v.x), __float2half_rn(v.y));
    __half2 b(__float2half_rn(v.z), __float2half_rn(v.w));
    uint2 o;
    o.x = *reinterpret_cast<uint32_t*>(&a);
    o.y = *reinterpret_cast<uint32_t*>(&b);
    ((uint2*)out)[i4] = o;
}

__global__ void __launch_bounds__(256) conv_wq2_k(
    const float* __restrict__ in, __half* __restrict__ out)
{
    const long idx = (long)blockIdx.x * 256 + threadIdx.x;
    const int r = (int)(idx >> 7);
    const int c = (int)(idx & 127) * 4;
    float4 v = *(const float4*)(in + (long)r * CDIM + c);
    __half h0, h1, h2, h3, l0, l1, l2, l3;
    split_h(v.x, h0, l0); split_h(v.y, h1, l1);
    split_h(v.z, h2, l2); split_h(v.w, h3, l3);
    __half* oh = out + (long)r * CDIM + c;
    *(uint2*)(oh)                     = make_uint2(pkh(h0, h1), pkh(h2, h3));
    *(uint2*)(oh + (long)CDIM * CDIM) = make_uint2(pkh(l0, l1), pkh(l2, l3));
}

// ---------------------------------------------------------------------------
extern "C" void kernel_launch(void* const* d_in, const int* in_sizes, int n_in,
                              void* d_out, int out_size)
{
    const float *x = nullptr, *w_qkv = nullptr, *w_out = nullptr, *b_out = nullptr;
    for (int i = 0; i < n_in; i++) {
        switch (in_sizes[i]) {
            case NB * CDIM * NSEQ:  x     = (const float*)d_in[i]; break;
            case 3 * CDIM * CDIM:   w_qkv = (const float*)d_in[i]; break;
            case CDIM * CDIM:       w_out = (const float*)d_in[i]; break;
            case CDIM:              b_out = (const float*)d_in[i]; break;
        }
    }
    float* out = (float*)d_out;

    float *sum_p, *part_p;
    __half *kvh_p, *xh_p, *wh_p, *wq2_p, *A2_p, *Mh_p;
    cudaGetSymbolAddress((void**)&kvh_p,  g_kvh);
    cudaGetSymbolAddress((void**)&sum_p,  g_sum);
    cudaGetSymbolAddress((void**)&part_p, g_part);
    cudaGetSymbolAddress((void**)&xh_p,   g_xh);
    cudaGetSymbolAddress((void**)&wh_p,   g_wh);
    cudaGetSymbolAddress((void**)&wq2_p,  g_wq2);
    cudaGetSymbolAddress((void**)&A2_p,   g_A2);
    cudaGetSymbolAddress((void**)&Mh_p,   g_Mh);

    static bool attr_set = false;
    if (!attr_set) {
        cudaFuncSetAttribute(gemm_h<false, true>,
                             cudaFuncAttributeMaxDynamicSharedMemorySize, G2SMEM);
        cudaFuncSetAttribute(gemm_h<true, false>,
                             cudaFuncAttributeMaxDynamicSharedMemorySize, G2SMEM);
        cudaFuncSetAttribute(gemm_m_k,
                             cudaFuncAttributeMaxDynamicSharedMemorySize, MSMEM);
        attr_set = true;
    }

    // converters
    conv_h_k<<<(KV * KREAL / 4 + 255) / 256, 256>>>(
        w_qkv + (long)CDIM * CDIM, wh_p, (long)KV * KREAL / 4);
    conv_wq2_k<<<(CDIM * 128) / 256, 256>>>(w_qkv, wq2_p);
    conv_h_k<<<((long)NB * CDIM * NSEQ / 4 + 255) / 256, 256>>>(
        x, xh_p, (long)NB * CDIM * NSEQ / 4);

    // kv = Wh @ xh -> fp16, exp fused on k rows
    {
        dim3 grid(NSEQ / 128, KV / 128, NB);
        gemm_h<false, true><<<grid, 128, G2SMEM>>>(wh_p, xh_p, kvh_p, nullptr,
                                                   0L, (long)CDIM * NSEQ,
                                                   (long)KV * NSEQ, NSEQ, NSEQ);
    }
    // normalization sums + context tensor GEMM
    rowsum_k<<<NB * CDIM, 256>>>(kvh_p, sum_p);
    {
        dim3 grid(NSPL, NB * HEADS);
        ctx64_k<<<grid, 128>>>(kvh_p, part_p);
    }
    // A2 = split(fold(w_out, reduce(part)/sums) * qscale)   (fused)
    {
        dim3 grid(HEADS, NB, 2);
        build_A2f_k<<<grid, 256>>>(w_out, part_p, sum_p, A2_p);
    }
    // Mh = fp16(A @ Wq) (exact split GEMM)
    {
        dim3 grid(CDIM / 128, CDIM / 128, NB);
        gemm_m_k<<<grid, 128, MSMEM>>>(A2_p, wq2_p, Mh_p,
                                       (long)CDIM * KP2, (long)CDIM * CDIM);
    }
    // out = Mh @ xh + b_out
    {
        dim3 grid(NSEQ / 128, CDIM / 128, NB);
        gemm_h<true, false><<<grid, 128, G2SMEM>>>(Mh_p, xh_p, out, b_out,
                                                   (long)CDIM * CDIM, (long)CDIM * NSEQ,
                                                   (long)CDIM * NSEQ, NSEQ, NSEQ);
    }
}